// round 11
// baseline (speedup 1.0000x reference)
#include <cuda_runtime.h>
#include <cuda_fp16.h>
#include <math.h>
#include <stdint.h>

// Problem constants (B=1)
#define T 2048
#define H 1024
#define II 4096
#define E 8

// Tiling: block 128(M) x 256(N), 8 warps of 64x64, fp16 single-term
#define BM 128
#define BN 256
#define KC 32              // K elems (fp16) per chunk
#define RSB 80             // smem row stride bytes (64B data + 16B pad)
#define STAGES 4
#define NTHREADS 256

#define ATB (BM * RSB)     // 10240 B
#define BTB (BN * RSB)     // 20480 B
#define STG_B (ATB + BTB)  // 30720 B per stage
#define SM_TOK   0
#define SM_TILES 1024
#define OFF_A(s) (SM_TILES + (s) * STG_B)
#define OFF_B(s) (SM_TILES + (s) * STG_B + ATB)
#define SMEM_TOTAL (SM_TILES + STAGES * STG_B)   // 123904 B

// ---------------- scratch (device globals) ----------------
__device__ int   g_cnt[E];
__device__ int   g_tok[E][T];
__device__ float g_wt[E][T];
__device__ __half g_xh[(size_t)T * H];
__device__ __half g_w1h[(size_t)E * II * H];
__device__ __half g_w2h[(size_t)E * H * II];
__device__ __half g_hid[(size_t)2 * T * II];

// ---------------- helpers ----------------
__device__ __forceinline__ uint32_t smem_u32(const void* p) {
    uint32_t a;
    asm("{ .reg .u64 t; cvta.to.shared.u64 t, %1; cvt.u32.u64 %0, t; }" : "=r"(a) : "l"(p));
    return a;
}
__device__ __forceinline__ void cp16(uint32_t s, const void* g) {
    asm volatile("cp.async.cg.shared.global [%0], [%1], 16;" :: "r"(s), "l"(g));
}
__device__ __forceinline__ void cp_commit() {
    asm volatile("cp.async.commit_group;" ::: "memory");
}
template <int N>
__device__ __forceinline__ void cp_wait() {
    asm volatile("cp.async.wait_group %0;" :: "n"(N) : "memory");
}
__device__ __forceinline__ void ldsm4(uint32_t* r, uint32_t addr) {
    asm volatile("ldmatrix.sync.aligned.m8n8.x4.shared.b16 {%0,%1,%2,%3}, [%4];"
                 : "=r"(r[0]), "=r"(r[1]), "=r"(r[2]), "=r"(r[3]) : "r"(addr));
}
__device__ __forceinline__ void mma16816(float* d, const uint32_t* a, const uint32_t* b) {
    asm volatile("mma.sync.aligned.m16n8k16.row.col.f32.f16.f16.f32 "
                 "{%0,%1,%2,%3}, {%4,%5,%6,%7}, {%8,%9}, {%0,%1,%2,%3};"
                 : "+f"(d[0]), "+f"(d[1]), "+f"(d[2]), "+f"(d[3])
                 : "r"(a[0]), "r"(a[1]), "r"(a[2]), "r"(a[3]), "r"(b[0]), "r"(b[1]));
}
__device__ __forceinline__ uint32_t pack_h2(float a, float b) {
    __half2 h = __floats2half2_rn(a, b);
    return *(uint32_t*)&h;
}

// ---------------- kernel: fp32 -> fp16 convert, 4x ILP per thread ----------------
__global__ void cvt_kernel(const float* __restrict__ src,
                           __half* __restrict__ dst, int n4) {
    int base = blockIdx.x * (blockDim.x * 4) + threadIdx.x;
    float4 v[4];
    int idx[4];
    #pragma unroll
    for (int j = 0; j < 4; j++) {
        idx[j] = base + j * blockDim.x;
        if (idx[j] < n4) v[j] = ((const float4*)src)[idx[j]];
    }
    #pragma unroll
    for (int j = 0; j < 4; j++) {
        if (idx[j] < n4) {
            uint2 u;
            u.x = pack_h2(v[j].x, v[j].y);
            u.y = pack_h2(v[j].z, v[j].w);
            ((uint2*)dst)[idx[j]] = u;
        }
    }
}

// ---------------- kernel 0: zero output + counters ----------------
__global__ void zero_kernel(float* __restrict__ out) {
    int i = blockIdx.x * blockDim.x + threadIdx.x;
    if (i < T * H) out[i] = 0.f;
    if (i < E) g_cnt[i] = 0;
}

// ---------------- kernel 1: gate -> top2 -> grouped lists ----------------
__global__ __launch_bounds__(256) void gate_kernel(const float* __restrict__ x,
                                                   const float* __restrict__ gw) {
    int t = blockIdx.x;
    int warp = threadIdx.x >> 5;
    int lane = threadIdx.x & 31;

    const float4* xr = (const float4*)(x + (size_t)t * H);
    const float4* gr = (const float4*)(gw + (size_t)warp * H);
    float s = 0.f;
    for (int j = lane; j < H / 4; j += 32) {
        float4 a = xr[j], b = gr[j];
        s += a.x * b.x + a.y * b.y + a.z * b.z + a.w * b.w;
    }
    #pragma unroll
    for (int o = 16; o > 0; o >>= 1) s += __shfl_xor_sync(0xffffffffu, s, o);

    __shared__ float lg[E];
    if (lane == 0) lg[warp] = s;
    __syncthreads();

    if (threadIdx.x == 0) {
        int e0 = 0;
        #pragma unroll
        for (int e = 1; e < E; e++) if (lg[e] > lg[e0]) e0 = e;
        int e1 = -1;
        #pragma unroll
        for (int e = 0; e < E; e++) {
            if (e == e0) continue;
            if (e1 < 0 || lg[e] > lg[e1]) e1 = e;
        }
        float d = expf(lg[e1] - lg[e0]);
        float w0 = 1.f / (1.f + d);
        float w1v = d / (1.f + d);
        int p0 = atomicAdd(&g_cnt[e0], 1);
        g_tok[e0][p0] = t; g_wt[e0][p0] = w0;
        int p1 = atomicAdd(&g_cnt[e1], 1);
        g_tok[e1][p1] = t; g_wt[e1][p1] = w1v;
    }
}

// ---------------- mainloop mma over one stage (64x64 warp tile, fp16) ----------------
__device__ __forceinline__ void mma_stage(uint32_t sb, int stage, int warp_m, int warp_n,
                                          int lane, float (*acc)[8][4]) {
    int lr = lane & 15;
    uint32_t lc16 = (lane >> 4) * 16;
    uint32_t a_b = sb + OFF_A(stage), b_b = sb + OFF_B(stage);
    #pragma unroll
    for (int kk = 0; kk < 2; kk++) {
        uint32_t colb = kk * 32 + lc16;
        uint32_t A[4][4];
        #pragma unroll
        for (int im = 0; im < 4; im++) {
            uint32_t aoff = (uint32_t)(warp_m * 64 + im * 16 + lr) * RSB + colb;
            ldsm4(A[im], a_b + aoff);
        }
        #pragma unroll
        for (int in2 = 0; in2 < 4; in2++) {
            uint32_t boff = (uint32_t)(warp_n * 64 + in2 * 16 + lr) * RSB + colb;
            uint32_t t[4];
            ldsm4(t, b_b + boff);
            uint32_t B0[2] = {t[0], t[2]}, B1[2] = {t[1], t[3]};
            #pragma unroll
            for (int im = 0; im < 4; im++) {
                mma16816(acc[im][2 * in2],     A[im], B0);
                mma16816(acc[im][2 * in2 + 1], A[im], B1);
            }
        }
    }
}

// ---------------- kernel 2: grouped GEMM1 + silu ----------------
__global__ __launch_bounds__(NTHREADS, 1) void gemm1_tc() {
    extern __shared__ char smem[];
    int e = blockIdx.z;
    int cnt = g_cnt[e];
    int m0 = blockIdx.y * BM;
    if (m0 >= cnt) return;
    int n0 = blockIdx.x * BN;
    int base = 0;
    #pragma unroll
    for (int i = 0; i < E; i++) if (i < e) base += g_cnt[i];
    int tid = threadIdx.x, wid = tid >> 5, lane = tid & 31;

    int* stok = (int*)(smem + SM_TOK);
    if (tid < BM) {
        int m = m0 + tid;
        stok[tid] = g_tok[e][m < cnt ? m : cnt - 1];
    }
    __syncthreads();
    uint32_t sb = smem_u32(smem);

    // A staging: row = tid/2 (0..127), half = tid&1 -> 32B (two cp16)
    int arow = tid >> 1, ahalf = tid & 1;
    const __half* pa = g_xh + (size_t)stok[arow] * H + ahalf * 16;
    uint32_t soffA = (uint32_t)arow * RSB + ahalf * 32;
    // B staging: row = tid (0..255) -> full 64B row (four cp16)
    const __half* pb = g_w1h + (size_t)e * II * H + (size_t)(n0 + tid) * H;
    uint32_t soffB = (uint32_t)tid * RSB;

    int warp_m = wid >> 2, warp_n = wid & 3;

    float acc[4][8][4];
    #pragma unroll
    for (int i = 0; i < 4; i++)
        #pragma unroll
        for (int j = 0; j < 8; j++)
            #pragma unroll
            for (int q = 0; q < 4; q++) acc[i][j][q] = 0.f;

    const int NK = H / KC;   // 32

    #pragma unroll
    for (int s = 0; s < STAGES - 1; s++) {
        int ko = s * KC;
        cp16(sb + OFF_A(s) + soffA,      pa + ko);
        cp16(sb + OFF_A(s) + soffA + 16, pa + ko + 8);
        #pragma unroll
        for (int j = 0; j < 4; j++)
            cp16(sb + OFF_B(s) + soffB + j * 16, pb + ko + j * 8);
        cp_commit();
    }

    for (int kc = 0; kc < NK; kc++) {
        cp_wait<STAGES - 2>();
        __syncthreads();
        int kn = kc + STAGES - 1;
        if (kn < NK) {
            int s = kn % STAGES;
            int ko = kn * KC;
            cp16(sb + OFF_A(s) + soffA,      pa + ko);
            cp16(sb + OFF_A(s) + soffA + 16, pa + ko + 8);
            #pragma unroll
            for (int j = 0; j < 4; j++)
                cp16(sb + OFF_B(s) + soffB + j * 16, pb + ko + j * 8);
        }
        cp_commit();
        mma_stage(sb, kc % STAGES, warp_m, warp_n, lane, acc);
    }

    // epilogue: silu -> fp16 hid
    int quad = lane >> 2, tq = lane & 3;
    #pragma unroll
    for (int im = 0; im < 4; im++) {
        int mA = m0 + warp_m * 64 + im * 16 + quad;
        int mB = mA + 8;
        bool aA = (mA < cnt), aB = (mB < cnt);
        size_t roA = aA ? (size_t)(base + mA) * II : 0;
        size_t roB = aB ? (size_t)(base + mB) * II : 0;
        #pragma unroll
        for (int in = 0; in < 8; in++) {
            int col = n0 + warp_n * 64 + in * 8 + tq * 2;
            if (aA) {
                float v0 = acc[im][in][0], v1 = acc[im][in][1];
                v0 = v0 / (1.f + __expf(-v0));
                v1 = v1 / (1.f + __expf(-v1));
                *(uint32_t*)(g_hid + roA + col) = pack_h2(v0, v1);
            }
            if (aB) {
                float v0 = acc[im][in][2], v1 = acc[im][in][3];
                v0 = v0 / (1.f + __expf(-v0));
                v1 = v1 / (1.f + __expf(-v1));
                *(uint32_t*)(g_hid + roB + col) = pack_h2(v0, v1);
            }
        }
    }
}

// ---------------- kernel 3: grouped GEMM2 + scatter-add ----------------
__global__ __launch_bounds__(NTHREADS, 1) void gemm2_tc(float* __restrict__ out) {
    extern __shared__ char smem[];
    int e = blockIdx.z;
    int cnt = g_cnt[e];
    int m0 = blockIdx.y * BM;
    if (m0 >= cnt) return;
    int n0 = blockIdx.x * BN;
    int base = 0;
    #pragma unroll
    for (int i = 0; i < E; i++) if (i < e) base += g_cnt[i];
    int tid = threadIdx.x, wid = tid >> 5, lane = tid & 31;
    uint32_t sb = smem_u32(smem);

    int arow = tid >> 1, ahalf = tid & 1;
    int am = m0 + arow; if (am >= cnt) am = cnt - 1;
    const __half* pa = g_hid + (size_t)(base + am) * II + ahalf * 16;
    uint32_t soffA = (uint32_t)arow * RSB + ahalf * 32;
    const __half* pb = g_w2h + (size_t)e * H * II + (size_t)(n0 + tid) * II;
    uint32_t soffB = (uint32_t)tid * RSB;

    int warp_m = wid >> 2, warp_n = wid & 3;

    float acc[4][8][4];
    #pragma unroll
    for (int i = 0; i < 4; i++)
        #pragma unroll
        for (int j = 0; j < 8; j++)
            #pragma unroll
            for (int q = 0; q < 4; q++) acc[i][j][q] = 0.f;

    const int NK = II / KC;  // 128

    #pragma unroll
    for (int s = 0; s < STAGES - 1; s++) {
        int ko = s * KC;
        cp16(sb + OFF_A(s) + soffA,      pa + ko);
        cp16(sb + OFF_A(s) + soffA + 16, pa + ko + 8);
        #pragma unroll
        for (int j = 0; j < 4; j++)
            cp16(sb + OFF_B(s) + soffB + j * 16, pb + ko + j * 8);
        cp_commit();
    }

    for (int kc = 0; kc < NK; kc++) {
        cp_wait<STAGES - 2>();
        __syncthreads();
        int kn = kc + STAGES - 1;
        if (kn < NK) {
            int s = kn % STAGES;
            int ko = kn * KC;
            cp16(sb + OFF_A(s) + soffA,      pa + ko);
            cp16(sb + OFF_A(s) + soffA + 16, pa + ko + 8);
            #pragma unroll
            for (int j = 0; j < 4; j++)
                cp16(sb + OFF_B(s) + soffB + j * 16, pb + ko + j * 8);
        }
        cp_commit();
        mma_stage(sb, kc % STAGES, warp_m, warp_n, lane, acc);
    }

    // epilogue: weighted scatter-add
    int quad = lane >> 2, tq = lane & 3;
    #pragma unroll
    for (int im = 0; im < 4; im++) {
        int mA = m0 + warp_m * 64 + im * 16 + quad;
        int mB = mA + 8;
        bool aA = (mA < cnt), aB = (mB < cnt);
        int tokA = aA ? g_tok[e][mA] : 0;  float wtA = aA ? g_wt[e][mA] : 0.f;
        int tokB = aB ? g_tok[e][mB] : 0;  float wtB = aB ? g_wt[e][mB] : 0.f;
        float* oA = out + (size_t)tokA * H;
        float* oB = out + (size_t)tokB * H;
        #pragma unroll
        for (int in = 0; in < 8; in++) {
            int col = n0 + warp_n * 64 + in * 8 + tq * 2;
            if (aA) {
                atomicAdd(oA + col,     wtA * acc[im][in][0]);
                atomicAdd(oA + col + 1, wtA * acc[im][in][1]);
            }
            if (aB) {
                atomicAdd(oB + col,     wtB * acc[im][in][2]);
                atomicAdd(oB + col + 1, wtB * acc[im][in][3]);
            }
        }
    }
}

// ---------------- launch ----------------
extern "C" void kernel_launch(void* const* d_in, const int* in_sizes, int n_in,
                              void* d_out, int out_size) {
    const float* x  = (const float*)d_in[0];   // [1,2048,1024]
    const float* gw = (const float*)d_in[1];   // [8,1024]
    const float* w1 = (const float*)d_in[2];   // [8,4096,1024]
    const float* w2 = (const float*)d_in[3];   // [8,1024,4096]
    float* out = (float*)d_out;                // [1,2048,1024]

    cudaFuncSetAttribute(gemm1_tc, cudaFuncAttributeMaxDynamicSharedMemorySize, SMEM_TOTAL);
    cudaFuncSetAttribute(gemm2_tc, cudaFuncAttributeMaxDynamicSharedMemorySize, SMEM_TOTAL);

    __half *xh, *w1h, *w2h;
    cudaGetSymbolAddress((void**)&xh,  g_xh);
    cudaGetSymbolAddress((void**)&w1h, g_w1h);
    cudaGetSymbolAddress((void**)&w2h, g_w2h);

    const int n4_x = T * H / 4;
    const int n4_w = E * II * H / 4;
    zero_kernel<<<(T * H + 255) / 256, 256>>>(out);                     // 1
    gate_kernel<<<T, 256>>>(x, gw);                                     // 2
    cvt_kernel<<<(n4_x + 1023) / 1024, 256>>>(x, xh, n4_x);             // 3
    cvt_kernel<<<(n4_w + 1023) / 1024, 256>>>(w1, w1h, n4_w);           // 4
    cvt_kernel<<<(n4_w + 1023) / 1024, 256>>>(w2, w2h, n4_w);           // 5
    gemm1_tc<<<dim3(II / BN, T / BM, E), NTHREADS, SMEM_TOTAL>>>();     // 6 (profiled)
    gemm2_tc<<<dim3(H / BN, T / BM, E), NTHREADS, SMEM_TOTAL>>>(out);   // 7
}

// round 13
// speedup vs baseline: 1.4804x; 1.4804x over previous
#include <cuda_runtime.h>
#include <cuda_fp16.h>
#include <math.h>
#include <stdint.h>

// Problem constants (B=1)
#define T 2048
#define H 1024
#define II 4096
#define E 8

// Tiling: block 128(M) x 256(N), 8 warps of 64x64, fp16 single-term
#define BM 128
#define BN 256
#define KC 32              // K elems (fp16) per chunk
#define RSB 80             // smem row stride bytes (64B data + 16B pad)
#define STAGES 4
#define NTHREADS 256

#define ATB (BM * RSB)     // 10240 B
#define BTB (BN * RSB)     // 20480 B
#define STG_B (ATB + BTB)  // 30720 B per stage
#define SM_TOK   0
#define SM_TILES 1024
#define OFF_A(s) (SM_TILES + (s) * STG_B)
#define OFF_B(s) (SM_TILES + (s) * STG_B + ATB)
#define SMEM_TOTAL (SM_TILES + STAGES * STG_B)   // 123904 B

// ---------------- scratch (device globals) ----------------
__device__ int   g_cnt[E];
__device__ int   g_off[E];
__device__ int   g_tok[E][T];
__device__ float g_wt[E][T];
__device__ __half g_xh[(size_t)T * H];
__device__ __half g_w1h[(size_t)E * II * H];
__device__ __half g_w2h[(size_t)E * H * II];
__device__ __half g_hid[(size_t)2 * T * II];

// ---------------- helpers ----------------
__device__ __forceinline__ uint32_t smem_u32(const void* p) {
    uint32_t a;
    asm("{ .reg .u64 t; cvta.to.shared.u64 t, %1; cvt.u32.u64 %0, t; }" : "=r"(a) : "l"(p));
    return a;
}
__device__ __forceinline__ void cp16(uint32_t s, const void* g) {
    asm volatile("cp.async.cg.shared.global [%0], [%1], 16;" :: "r"(s), "l"(g));
}
__device__ __forceinline__ void cp_commit() {
    asm volatile("cp.async.commit_group;" ::: "memory");
}
template <int N>
__device__ __forceinline__ void cp_wait() {
    asm volatile("cp.async.wait_group %0;" :: "n"(N) : "memory");
}
__device__ __forceinline__ void ldsm4(uint32_t* r, uint32_t addr) {
    asm volatile("ldmatrix.sync.aligned.m8n8.x4.shared.b16 {%0,%1,%2,%3}, [%4];"
                 : "=r"(r[0]), "=r"(r[1]), "=r"(r[2]), "=r"(r[3]) : "r"(addr));
}
__device__ __forceinline__ void mma16816(float* d, const uint32_t* a, const uint32_t* b) {
    asm volatile("mma.sync.aligned.m16n8k16.row.col.f32.f16.f16.f32 "
                 "{%0,%1,%2,%3}, {%4,%5,%6,%7}, {%8,%9}, {%0,%1,%2,%3};"
                 : "+f"(d[0]), "+f"(d[1]), "+f"(d[2]), "+f"(d[3])
                 : "r"(a[0]), "r"(a[1]), "r"(a[2]), "r"(a[3]), "r"(b[0]), "r"(b[1]));
}
__device__ __forceinline__ uint32_t pack_h2(float a, float b) {
    __half2 h = __floats2half2_rn(a, b);
    return *(uint32_t*)&h;
}

// ---------------- kernel: fp32 -> fp16 convert, 4x ILP per thread ----------------
__global__ void cvt_kernel(const float* __restrict__ src,
                           __half* __restrict__ dst, int n4) {
    int base = blockIdx.x * (blockDim.x * 4) + threadIdx.x;
    float4 v[4];
    int idx[4];
    #pragma unroll
    for (int j = 0; j < 4; j++) {
        idx[j] = base + j * blockDim.x;
        if (idx[j] < n4) v[j] = ((const float4*)src)[idx[j]];
    }
    #pragma unroll
    for (int j = 0; j < 4; j++) {
        if (idx[j] < n4) {
            uint2 u;
            u.x = pack_h2(v[j].x, v[j].y);
            u.y = pack_h2(v[j].z, v[j].w);
            ((uint2*)dst)[idx[j]] = u;
        }
    }
}

// ---------------- kernel 0: zero output + counters ----------------
__global__ void zero_kernel(float* __restrict__ out) {
    int i = blockIdx.x * blockDim.x + threadIdx.x;
    if (i < T * H) out[i] = 0.f;
    if (i < E) g_cnt[i] = 0;
}

// ---------------- kernel 1: gate -> top2 -> grouped lists ----------------
__global__ __launch_bounds__(256) void gate_kernel(const float* __restrict__ x,
                                                   const float* __restrict__ gw) {
    int t = blockIdx.x;
    int warp = threadIdx.x >> 5;
    int lane = threadIdx.x & 31;

    const float4* xr = (const float4*)(x + (size_t)t * H);
    const float4* gr = (const float4*)(gw + (size_t)warp * H);
    float s = 0.f;
    for (int j = lane; j < H / 4; j += 32) {
        float4 a = xr[j], b = gr[j];
        s += a.x * b.x + a.y * b.y + a.z * b.z + a.w * b.w;
    }
    #pragma unroll
    for (int o = 16; o > 0; o >>= 1) s += __shfl_xor_sync(0xffffffffu, s, o);

    __shared__ float lg[E];
    if (lane == 0) lg[warp] = s;
    __syncthreads();

    if (threadIdx.x == 0) {
        int e0 = 0;
        #pragma unroll
        for (int e = 1; e < E; e++) if (lg[e] > lg[e0]) e0 = e;
        int e1 = -1;
        #pragma unroll
        for (int e = 0; e < E; e++) {
            if (e == e0) continue;
            if (e1 < 0 || lg[e] > lg[e1]) e1 = e;
        }
        float d = expf(lg[e1] - lg[e0]);
        float w0 = 1.f / (1.f + d);
        float w1v = d / (1.f + d);
        int p0 = atomicAdd(&g_cnt[e0], 1);
        g_tok[e0][p0] = t; g_wt[e0][p0] = w0;
        int p1 = atomicAdd(&g_cnt[e1], 1);
        g_tok[e1][p1] = t; g_wt[e1][p1] = w1v;
    }
}

// ---------------- kernel 1b: exclusive prefix ----------------
__global__ void prefix_kernel() {
    if (threadIdx.x == 0 && blockIdx.x == 0) {
        int acc = 0;
        #pragma unroll
        for (int e = 0; e < E; e++) { g_off[e] = acc; acc += g_cnt[e]; }
    }
}

// ---------------- mainloop mma over one stage (64x64 warp tile, fp16) ----------------
__device__ __forceinline__ void mma_stage(uint32_t sb, int stage, int warp_m, int warp_n,
                                          int lane, float (*acc)[8][4]) {
    int lr = lane & 15;
    uint32_t lc16 = (lane >> 4) * 16;
    uint32_t a_b = sb + OFF_A(stage), b_b = sb + OFF_B(stage);
    #pragma unroll
    for (int kk = 0; kk < 2; kk++) {
        uint32_t colb = kk * 32 + lc16;
        uint32_t A[4][4];
        #pragma unroll
        for (int im = 0; im < 4; im++) {
            uint32_t aoff = (uint32_t)(warp_m * 64 + im * 16 + lr) * RSB + colb;
            ldsm4(A[im], a_b + aoff);
        }
        #pragma unroll
        for (int in2 = 0; in2 < 4; in2++) {
            uint32_t boff = (uint32_t)(warp_n * 64 + in2 * 16 + lr) * RSB + colb;
            uint32_t t[4];
            ldsm4(t, b_b + boff);
            uint32_t B0[2] = {t[0], t[2]}, B1[2] = {t[1], t[3]};
            #pragma unroll
            for (int im = 0; im < 4; im++) {
                mma16816(acc[im][2 * in2],     A[im], B0);
                mma16816(acc[im][2 * in2 + 1], A[im], B1);
            }
        }
    }
}

// ---------------- kernel 2: grouped GEMM1 + silu ----------------
__global__ __launch_bounds__(NTHREADS, 1) void gemm1_tc() {
    extern __shared__ char smem[];
    int e = blockIdx.z;
    int cnt = g_cnt[e];
    int m0 = blockIdx.y * BM;
    if (m0 >= cnt) return;
    int n0 = blockIdx.x * BN;
    int base = g_off[e];
    int tid = threadIdx.x, wid = tid >> 5, lane = tid & 31;

    int* stok = (int*)(smem + SM_TOK);
    if (tid < BM) {
        int m = m0 + tid;
        stok[tid] = g_tok[e][m < cnt ? m : cnt - 1];
    }
    __syncthreads();
    uint32_t sb = smem_u32(smem);

    // A staging: row = tid/2 (0..127), half = tid&1 -> 32B (two cp16)
    int arow = tid >> 1, ahalf = tid & 1;
    const __half* pa = g_xh + (size_t)stok[arow] * H + ahalf * 16;
    uint32_t soffA = (uint32_t)arow * RSB + ahalf * 32;
    // B staging: row = tid (0..255) -> full 64B row (four cp16)
    const __half* pb = g_w1h + (size_t)e * II * H + (size_t)(n0 + tid) * H;
    uint32_t soffB = (uint32_t)tid * RSB;

    int warp_m = wid >> 2, warp_n = wid & 3;

    float acc[4][8][4];
    #pragma unroll
    for (int i = 0; i < 4; i++)
        #pragma unroll
        for (int j = 0; j < 8; j++)
            #pragma unroll
            for (int q = 0; q < 4; q++) acc[i][j][q] = 0.f;

    const int NK = H / KC;   // 32

    #pragma unroll
    for (int s = 0; s < STAGES - 1; s++) {
        int ko = s * KC;
        cp16(sb + OFF_A(s) + soffA,      pa + ko);
        cp16(sb + OFF_A(s) + soffA + 16, pa + ko + 8);
        #pragma unroll
        for (int j = 0; j < 4; j++)
            cp16(sb + OFF_B(s) + soffB + j * 16, pb + ko + j * 8);
        cp_commit();
    }

    for (int kc = 0; kc < NK; kc++) {
        cp_wait<STAGES - 2>();
        __syncthreads();
        int kn = kc + STAGES - 1;
        if (kn < NK) {
            int s = kn % STAGES;
            int ko = kn * KC;
            cp16(sb + OFF_A(s) + soffA,      pa + ko);
            cp16(sb + OFF_A(s) + soffA + 16, pa + ko + 8);
            #pragma unroll
            for (int j = 0; j < 4; j++)
                cp16(sb + OFF_B(s) + soffB + j * 16, pb + ko + j * 8);
        }
        cp_commit();
        mma_stage(sb, kc % STAGES, warp_m, warp_n, lane, acc);
    }

    // epilogue: silu -> fp16 hid
    int quad = lane >> 2, tq = lane & 3;
    #pragma unroll
    for (int im = 0; im < 4; im++) {
        int mA = m0 + warp_m * 64 + im * 16 + quad;
        int mB = mA + 8;
        bool aA = (mA < cnt), aB = (mB < cnt);
        size_t roA = aA ? (size_t)(base + mA) * II : 0;
        size_t roB = aB ? (size_t)(base + mB) * II : 0;
        #pragma unroll
        for (int in = 0; in < 8; in++) {
            int col = n0 + warp_n * 64 + in * 8 + tq * 2;
            if (aA) {
                float v0 = acc[im][in][0], v1 = acc[im][in][1];
                v0 = v0 / (1.f + __expf(-v0));
                v1 = v1 / (1.f + __expf(-v1));
                *(uint32_t*)(g_hid + roA + col) = pack_h2(v0, v1);
            }
            if (aB) {
                float v0 = acc[im][in][2], v1 = acc[im][in][3];
                v0 = v0 / (1.f + __expf(-v0));
                v1 = v1 / (1.f + __expf(-v1));
                *(uint32_t*)(g_hid + roB + col) = pack_h2(v0, v1);
            }
        }
    }
}

// ---------------- kernel 3: grouped GEMM2 + scatter-add ----------------
__global__ __launch_bounds__(NTHREADS, 1) void gemm2_tc(float* __restrict__ out) {
    extern __shared__ char smem[];
    int e = blockIdx.z;
    int cnt = g_cnt[e];
    int m0 = blockIdx.y * BM;
    if (m0 >= cnt) return;
    int n0 = blockIdx.x * BN;
    int base = g_off[e];
    int tid = threadIdx.x, wid = tid >> 5, lane = tid & 31;
    uint32_t sb = smem_u32(smem);

    int arow = tid >> 1, ahalf = tid & 1;
    int am = m0 + arow; if (am >= cnt) am = cnt - 1;
    const __half* pa = g_hid + (size_t)(base + am) * II + ahalf * 16;
    uint32_t soffA = (uint32_t)arow * RSB + ahalf * 32;
    const __half* pb = g_w2h + (size_t)e * H * II + (size_t)(n0 + tid) * II;
    uint32_t soffB = (uint32_t)tid * RSB;

    int warp_m = wid >> 2, warp_n = wid & 3;

    float acc[4][8][4];
    #pragma unroll
    for (int i = 0; i < 4; i++)
        #pragma unroll
        for (int j = 0; j < 8; j++)
            #pragma unroll
            for (int q = 0; q < 4; q++) acc[i][j][q] = 0.f;

    const int NK = II / KC;  // 128

    #pragma unroll
    for (int s = 0; s < STAGES - 1; s++) {
        int ko = s * KC;
        cp16(sb + OFF_A(s) + soffA,      pa + ko);
        cp16(sb + OFF_A(s) + soffA + 16, pa + ko + 8);
        #pragma unroll
        for (int j = 0; j < 4; j++)
            cp16(sb + OFF_B(s) + soffB + j * 16, pb + ko + j * 8);
        cp_commit();
    }

    for (int kc = 0; kc < NK; kc++) {
        cp_wait<STAGES - 2>();
        __syncthreads();
        int kn = kc + STAGES - 1;
        if (kn < NK) {
            int s = kn % STAGES;
            int ko = kn * KC;
            cp16(sb + OFF_A(s) + soffA,      pa + ko);
            cp16(sb + OFF_A(s) + soffA + 16, pa + ko + 8);
            #pragma unroll
            for (int j = 0; j < 4; j++)
                cp16(sb + OFF_B(s) + soffB + j * 16, pb + ko + j * 8);
        }
        cp_commit();
        mma_stage(sb, kc % STAGES, warp_m, warp_n, lane, acc);
    }

    // epilogue: weighted scatter-add
    int quad = lane >> 2, tq = lane & 3;
    #pragma unroll
    for (int im = 0; im < 4; im++) {
        int mA = m0 + warp_m * 64 + im * 16 + quad;
        int mB = mA + 8;
        bool aA = (mA < cnt), aB = (mB < cnt);
        int tokA = aA ? g_tok[e][mA] : 0;  float wtA = aA ? g_wt[e][mA] : 0.f;
        int tokB = aB ? g_tok[e][mB] : 0;  float wtB = aB ? g_wt[e][mB] : 0.f;
        float* oA = out + (size_t)tokA * H;
        float* oB = out + (size_t)tokB * H;
        #pragma unroll
        for (int in = 0; in < 8; in++) {
            int col = n0 + warp_n * 64 + in * 8 + tq * 2;
            if (aA) {
                atomicAdd(oA + col,     wtA * acc[im][in][0]);
                atomicAdd(oA + col + 1, wtA * acc[im][in][1]);
            }
            if (aB) {
                atomicAdd(oB + col,     wtB * acc[im][in][2]);
                atomicAdd(oB + col + 1, wtB * acc[im][in][3]);
            }
        }
    }
}

// ---------------- launch ----------------
extern "C" void kernel_launch(void* const* d_in, const int* in_sizes, int n_in,
                              void* d_out, int out_size) {
    const float* x  = (const float*)d_in[0];   // [1,2048,1024]
    const float* gw = (const float*)d_in[1];   // [8,1024]
    const float* w1 = (const float*)d_in[2];   // [8,4096,1024]
    const float* w2 = (const float*)d_in[3];   // [8,1024,4096]
    float* out = (float*)d_out;                // [1,2048,1024]

    cudaFuncSetAttribute(gemm1_tc, cudaFuncAttributeMaxDynamicSharedMemorySize, SMEM_TOTAL);
    cudaFuncSetAttribute(gemm2_tc, cudaFuncAttributeMaxDynamicSharedMemorySize, SMEM_TOTAL);

    __half *xh, *w1h, *w2h;
    cudaGetSymbolAddress((void**)&xh,  g_xh);
    cudaGetSymbolAddress((void**)&w1h, g_w1h);
    cudaGetSymbolAddress((void**)&w2h, g_w2h);

    const int n4_x = T * H / 4;
    const int n4_w = E * II * H / 4;
    zero_kernel<<<(T * H + 255) / 256, 256>>>(out);                     // 1
    gate_kernel<<<T, 256>>>(x, gw);                                     // 2
    prefix_kernel<<<1, 32>>>();                                         // 3
    cvt_kernel<<<(n4_x + 1023) / 1024, 256>>>(x, xh, n4_x);             // 4
    cvt_kernel<<<(n4_w + 1023) / 1024, 256>>>(w1, w1h, n4_w);           // 5
    cvt_kernel<<<(n4_w + 1023) / 1024, 256>>>(w2, w2h, n4_w);           // 6
    gemm1_tc<<<dim3(II / BN, T / BM, E), NTHREADS, SMEM_TOTAL>>>();     // 7
    gemm2_tc<<<dim3(H / BN, T / BM, E), NTHREADS, SMEM_TOTAL>>>(out);   // 8
}